// round 9
// baseline (speedup 1.0000x reference)
#include <cuda_runtime.h>

#define N_NODES 50000
#define R_REL 51
#define F_DIM 32
#define E_DIM 32
#define C_DIM 16
#define B_BASES 30
#define NNZ_MAX 2001024
#define CHUNKS 8            // chunks per relation bucket for layer kernels

typedef unsigned long long ull;
typedef unsigned int uint;

// ---- scratch (__device__ globals: no allocation allowed) -------------------
__device__ float g_w1[R_REL * F_DIM * E_DIM];            // [r][f][e]  208 KB
__device__ float g_w2[R_REL * E_DIM * C_DIM];            // [r][h][c]  104 KB
__device__ __align__(16) float g_h1[N_NODES * E_DIM];    // 6.4 MB
__device__ unsigned g_hist[R_REL];
__device__ unsigned g_cursor[R_REL];   // post-scatter: inclusive prefix end of bucket r
__device__ unsigned g_done;
__device__ unsigned g_nm[NNZ_MAX];                       // (n<<16)|m (both <65536)
__device__ float    g_v[NNZ_MAX];

// ---- packed f32x2 helpers --------------------------------------------------
__device__ __forceinline__ ull pack2(float lo, float hi) {
    ull r; asm("mov.b64 %0,{%1,%2};" : "=l"(r) : "f"(lo), "f"(hi)); return r;
}
__device__ __forceinline__ void unpack2(ull v, float& lo, float& hi) {
    asm("mov.b64 {%0,%1},%2;" : "=f"(lo), "=f"(hi) : "l"(v));
}
__device__ __forceinline__ ull ffma2(ull a, ull b, ull c) {
    ull d; asm("fma.rn.f32x2 %0,%1,%2,%3;" : "=l"(d) : "l"(a), "l"(b), "l"(c)); return d;
}
__device__ __forceinline__ ull fadd2(ull a, ull b) {
    ull d; asm("add.rn.f32x2 %0,%1,%2;" : "=l"(d) : "l"(a), "l"(b)); return d;
}
__device__ __forceinline__ ull fmul2(ull a, ull b) {
    ull d; asm("mul.rn.f32x2 %0,%1,%2;" : "=l"(d) : "l"(a), "l"(b)); return d;
}
__device__ __forceinline__ void red_add_v4(float* p, float a, float b, float c, float d) {
    asm volatile("red.global.add.v4.f32 [%0], {%1,%2,%3,%4};"
                 :: "l"(p), "f"(a), "f"(b), "f"(c), "f"(d) : "memory");
}
__device__ __forceinline__ void red_add_v2(float* p, float a, float b) {
    asm volatile("red.global.add.v2.f32 [%0], {%1,%2};"
                 :: "l"(p), "f"(a), "f"(b) : "memory");
}
__device__ __forceinline__ ull shfl_xor_u64(ull v, int mask) {
    uint lo = (uint)v, hi = (uint)(v >> 32);
    lo = __shfl_xor_sync(0xffffffffu, lo, mask);
    hi = __shfl_xor_sync(0xffffffffu, hi, mask);
    return ((ull)hi << 32) | lo;
}

// ---------------------------------------------------------------------------
// Fused: per-relation weights + zero g_hist/g_done + zero g_h1.
// ---------------------------------------------------------------------------
__global__ void compute_w_kernel(const float* __restrict__ comps1,
                                 const float* __restrict__ bases1,
                                 const float* __restrict__ comps2,
                                 const float* __restrict__ bases2) {
    int idx = blockIdx.x * blockDim.x + threadIdx.x;
    const int total1 = R_REL * F_DIM * E_DIM;
    const int total2 = R_REL * E_DIM * C_DIM;
    if (idx < total1) {
        int r = idx / (F_DIM * E_DIM);
        int fe = idx - r * (F_DIM * E_DIM);
        float acc = 0.f;
#pragma unroll
        for (int b = 0; b < B_BASES; b++)
            acc = fmaf(comps1[r * B_BASES + b], bases1[b * (F_DIM * E_DIM) + fe], acc);
        g_w1[idx] = acc;
    }
    if (idx < total2) {
        int r = idx / (E_DIM * C_DIM);
        int hc = idx - r * (E_DIM * C_DIM);
        float acc = 0.f;
#pragma unroll
        for (int b = 0; b < B_BASES; b++)
            acc = fmaf(comps2[r * B_BASES + b], bases2[b * (E_DIM * C_DIM) + hc], acc);
        g_w2[idx] = acc;
    }
    if (idx < R_REL) g_hist[idx] = 0;
    if (idx == 0) g_done = 0;
    float4* h4 = (float4*)g_h1;
    const int nh4 = N_NODES * E_DIM / 4;
    for (int i = idx; i < nh4; i += gridDim.x * blockDim.x)
        h4[i] = make_float4(0.f, 0.f, 0.f, 0.f);
}

// ---------------------------------------------------------------------------
// Fused: histogram + (last block) exclusive-scan -> g_cursor + out = bias2.
// ---------------------------------------------------------------------------
__global__ void hist_kernel(const int* __restrict__ rows, int nnz,
                            float* __restrict__ out,
                            const float* __restrict__ bias2) {
    __shared__ unsigned sh[R_REL];
    if (threadIdx.x < R_REL) sh[threadIdx.x] = 0;
    __syncthreads();
    int gsz = gridDim.x * blockDim.x;
    for (int e = blockIdx.x * blockDim.x + threadIdx.x; e < nnz; e += gsz)
        atomicAdd(&sh[(unsigned)rows[e] / N_NODES], 1u);
    for (int i = blockIdx.x * blockDim.x + threadIdx.x; i < N_NODES * C_DIM; i += gsz)
        out[i] = bias2[i & (C_DIM - 1)];
    __syncthreads();
    if (threadIdx.x < R_REL) atomicAdd(&g_hist[threadIdx.x], sh[threadIdx.x]);
    __threadfence();
    __syncthreads();
    if (threadIdx.x == 0) {
        unsigned t = atomicAdd(&g_done, 1u);
        if (t == gridDim.x - 1) {
            unsigned s = 0;
            for (int r = 0; r < R_REL; r++) { g_cursor[r] = s; s += g_hist[r]; }
        }
    }
}

// Block-aggregated scatter into relation buckets.
// After this kernel, g_cursor[r] == end offset of bucket r (prefix-inclusive).
#define SCATTER_CHUNK 8192
__global__ void scatter_kernel(const int* __restrict__ rows,
                               const int* __restrict__ cols,
                               const float* __restrict__ vals, int nnz) {
    __shared__ unsigned cnt[R_REL];
    __shared__ unsigned base[R_REL];
    int start = blockIdx.x * SCATTER_CHUNK;
    if (start >= nnz) return;
    int end = min(start + SCATTER_CHUNK, nnz);

    if (threadIdx.x < R_REL) cnt[threadIdx.x] = 0;
    __syncthreads();
    for (int e = start + threadIdx.x; e < end; e += blockDim.x)
        atomicAdd(&cnt[(unsigned)rows[e] / N_NODES], 1u);
    __syncthreads();
    if (threadIdx.x < R_REL) {
        base[threadIdx.x] = atomicAdd(&g_cursor[threadIdx.x], cnt[threadIdx.x]);
        cnt[threadIdx.x] = 0;
    }
    __syncthreads();
    for (int e = start + threadIdx.x; e < end; e += blockDim.x) {
        unsigned row = (unsigned)rows[e];
        unsigned r = row / N_NODES;
        unsigned n = row - r * N_NODES;
        unsigned pos = base[r] + atomicAdd(&cnt[r], 1u);
        g_nm[pos] = (n << 16) | (unsigned)cols[e];
        g_v[pos]  = vals[e];
    }
}

__global__ void relu_bias_kernel(const float* __restrict__ bias1) {
    int idx = blockIdx.x * blockDim.x + threadIdx.x;
    const int n4 = N_NODES * E_DIM / 4;
    if (idx < n4) {
        float4* h4 = (float4*)g_h1;
        const float4* b4 = (const float4*)bias1;
        float4 v = h4[idx];
        float4 b = b4[idx & (E_DIM / 4 - 1)];
        v.x = fmaxf(v.x + b.x, 0.f);
        v.y = fmaxf(v.y + b.y, 0.f);
        v.z = fmaxf(v.z + b.z, 0.f);
        v.w = fmaxf(v.w + b.w, 0.f);
        h4[idx] = v;
    }
}

// ---------------------------------------------------------------------------
// Layer 1: CTA = (relation, chunk). Weights live in REGISTERS (no smem wall).
// 16 lanes per edge: fi = f-half (0/1, 16 f each), ej = output quad (0..7).
// Lane regs: w[16][2] ull = w1[r][fi*16+ff][ej*4 + {0,1 | 2,3}].
// Partial sums reduced over fi via one shfl_xor(8); fi==0 lanes do red.v4.
// ---------------------------------------------------------------------------
__global__ __launch_bounds__(256)
void layer1_kernel(const float* __restrict__ x) {
    const unsigned r     = blockIdx.x / CHUNKS;
    const unsigned chunk = blockIdx.x % CHUNKS;
    const unsigned lo  = (r == 0) ? 0u : g_cursor[r - 1];
    const unsigned hi  = g_cursor[r];
    const unsigned len = hi - lo;
    const unsigned cstart = lo + (unsigned)(((ull)len * chunk) / CHUNKS);
    const unsigned cend   = lo + (unsigned)(((ull)len * (chunk + 1)) / CHUNKS);
    if (cstart >= cend) return;

    const int lane = threadIdx.x & 31;
    const int wid  = threadIdx.x >> 5;            // 8 warps
    const int fi   = (lane >> 3) & 1;
    const int ej   = lane & 7;
    const int half = lane >> 4;                   // which edge of the pair

    // Preload weight slice: 32 ull (64 regs)
    const float* wb = g_w1 + r * (F_DIM * E_DIM) + (fi * 16) * E_DIM + ej * 4;
    ull w[16][2];
#pragma unroll
    for (int ff = 0; ff < 16; ff++) {
        w[ff][0] = *(const ull*)(wb + ff * E_DIM);
        w[ff][1] = *(const ull*)(wb + ff * E_DIM + 2);
    }

    for (unsigned b = cstart + wid * 2; b < cend; b += 16) {   // 8 warps * 2 edges
        unsigned eIdx = b + half;
        bool ok = eIdx < cend;
        unsigned ce = ok ? eIdx : cend - 1;
        unsigned nm = g_nm[ce];
        float v = ok ? g_v[ce] : 0.f;
        unsigned n = nm >> 16;
        unsigned m = nm & 0xFFFFu;

        const float4* xp = (const float4*)(x + (size_t)m * F_DIM + fi * 16);
        float4 x0 = xp[0], x1 = xp[1], x2 = xp[2], x3 = xp[3];
        float xs[16] = { x0.x, x0.y, x0.z, x0.w, x1.x, x1.y, x1.z, x1.w,
                         x2.x, x2.y, x2.z, x2.w, x3.x, x3.y, x3.z, x3.w };

        ull acc0 = 0, acc1 = 0;
#pragma unroll
        for (int ff = 0; ff < 16; ff++) {
            ull xpk = pack2(xs[ff], xs[ff]);
            acc0 = ffma2(xpk, w[ff][0], acc0);
            acc1 = ffma2(xpk, w[ff][1], acc1);
        }
        // reduce over fi (partner lane ^ 8)
        acc0 = fadd2(acc0, shfl_xor_u64(acc0, 8));
        acc1 = fadd2(acc1, shfl_xor_u64(acc1, 8));

        if (!(lane & 8)) {                        // fi == 0 lanes: 8 per edge
            ull vp = pack2(v, v);
            float a0, a1, a2, a3;
            unpack2(fmul2(acc0, vp), a0, a1);
            unpack2(fmul2(acc1, vp), a2, a3);
            red_add_v4(g_h1 + (size_t)n * E_DIM + ej * 4, a0, a1, a2, a3);
        }
    }
}

// ---------------------------------------------------------------------------
// Layer 2: same scheme. Lane owns c = cj*2, cj*2+1 (1 ull acc); w: 16 ull.
// ---------------------------------------------------------------------------
__global__ __launch_bounds__(256)
void layer2_kernel(float* __restrict__ out) {
    const unsigned r     = blockIdx.x / CHUNKS;
    const unsigned chunk = blockIdx.x % CHUNKS;
    const unsigned lo  = (r == 0) ? 0u : g_cursor[r - 1];
    const unsigned hi  = g_cursor[r];
    const unsigned len = hi - lo;
    const unsigned cstart = lo + (unsigned)(((ull)len * chunk) / CHUNKS);
    const unsigned cend   = lo + (unsigned)(((ull)len * (chunk + 1)) / CHUNKS);
    if (cstart >= cend) return;

    const int lane = threadIdx.x & 31;
    const int wid  = threadIdx.x >> 5;
    const int fi   = (lane >> 3) & 1;
    const int cj   = lane & 7;
    const int half = lane >> 4;

    const float* wb = g_w2 + r * (E_DIM * C_DIM) + (fi * 16) * C_DIM + cj * 2;
    ull w[16];
#pragma unroll
    for (int ff = 0; ff < 16; ff++)
        w[ff] = *(const ull*)(wb + ff * C_DIM);

    for (unsigned b = cstart + wid * 2; b < cend; b += 16) {
        unsigned eIdx = b + half;
        bool ok = eIdx < cend;
        unsigned ce = ok ? eIdx : cend - 1;
        unsigned nm = g_nm[ce];
        float v = ok ? g_v[ce] : 0.f;
        unsigned n = nm >> 16;
        unsigned m = nm & 0xFFFFu;

        const float4* hp = (const float4*)(g_h1 + (size_t)m * E_DIM + fi * 16);
        float4 x0 = hp[0], x1 = hp[1], x2 = hp[2], x3 = hp[3];
        float xs[16] = { x0.x, x0.y, x0.z, x0.w, x1.x, x1.y, x1.z, x1.w,
                         x2.x, x2.y, x2.z, x2.w, x3.x, x3.y, x3.z, x3.w };

        ull acc = 0;
#pragma unroll
        for (int ff = 0; ff < 16; ff++)
            acc = ffma2(pack2(xs[ff], xs[ff]), w[ff], acc);

        acc = fadd2(acc, shfl_xor_u64(acc, 8));

        if (!(lane & 8)) {
            float a0, a1;
            unpack2(fmul2(acc, pack2(v, v)), a0, a1);
            red_add_v2(out + (size_t)n * C_DIM + cj * 2, a0, a1);
        }
    }
}

// ---------------------------------------------------------------------------
extern "C" void kernel_launch(void* const* d_in, const int* in_sizes, int n_in,
                              void* d_out, int out_size) {
    const float* features = (const float*)d_in[0];
    const float* vals     = (const float*)d_in[1];
    const float* comps1   = (const float*)d_in[2];
    const float* bases1   = (const float*)d_in[3];
    const float* bias1    = (const float*)d_in[4];
    const float* comps2   = (const float*)d_in[5];
    const float* bases2   = (const float*)d_in[6];
    const float* bias2    = (const float*)d_in[7];
    const int*   rows     = (const int*)d_in[8];
    const int*   cols     = (const int*)d_in[9];
    float*       out      = (float*)d_out;
    const int    nnz      = in_sizes[8];

    // 1. weights + zero hist/done/h1
    compute_w_kernel<<<512, 256>>>(comps1, bases1, comps2, bases2);
    // 2. histogram + last-block scan + out=bias2
    hist_kernel<<<256, 256>>>(rows, nnz, out, bias2);
    // 3. bucket scatter (relation-sorted edge list; g_cursor -> bucket ends)
    scatter_kernel<<<(nnz + SCATTER_CHUNK - 1) / SCATTER_CHUNK, 512>>>(
        rows, cols, vals, nnz);
    // 4. layer 1 (register-resident weights, CTA per relation-chunk)
    layer1_kernel<<<R_REL * CHUNKS, 256>>>(features);
    // 5. bias + relu
    relu_bias_kernel<<<(N_NODES * E_DIM / 4 + 255) / 256, 256>>>(bias1);
    // 6. layer 2
    layer2_kernel<<<R_REL * CHUNKS, 256>>>(out);
}

// round 10
// speedup vs baseline: 1.3222x; 1.3222x over previous
#include <cuda_runtime.h>

#define N_NODES 50000
#define R_REL 51
#define F_DIM 32
#define E_DIM 32
#define C_DIM 16
#define B_BASES 30
#define NNZ_MAX 2001024
#define CHUNKS 16           // chunks per relation bucket for layer kernels

typedef unsigned long long ull;
typedef unsigned int uint;

// ---- scratch (__device__ globals: no allocation allowed) -------------------
__device__ float g_w1[R_REL * F_DIM * E_DIM];            // [r][f][e]  208 KB
__device__ float g_w2[R_REL * E_DIM * C_DIM];            // [r][h][c]  104 KB
__device__ __align__(16) float g_h1[N_NODES * E_DIM];    // 6.4 MB
__device__ unsigned g_hist[R_REL];
__device__ unsigned g_cursor[R_REL];   // post-scatter: inclusive prefix end of bucket r
__device__ unsigned g_done;
__device__ unsigned g_nm[NNZ_MAX];                       // (n<<16)|m (both <65536)
__device__ float    g_v[NNZ_MAX];

// ---- packed f32x2 helpers --------------------------------------------------
__device__ __forceinline__ ull pack2(float lo, float hi) {
    ull r; asm("mov.b64 %0,{%1,%2};" : "=l"(r) : "f"(lo), "f"(hi)); return r;
}
__device__ __forceinline__ void unpack2(ull v, float& lo, float& hi) {
    asm("mov.b64 {%0,%1},%2;" : "=f"(lo), "=f"(hi) : "l"(v));
}
__device__ __forceinline__ ull ffma2(ull a, ull b, ull c) {
    ull d; asm("fma.rn.f32x2 %0,%1,%2,%3;" : "=l"(d) : "l"(a), "l"(b), "l"(c)); return d;
}
__device__ __forceinline__ ull fadd2(ull a, ull b) {
    ull d; asm("add.rn.f32x2 %0,%1,%2;" : "=l"(d) : "l"(a), "l"(b)); return d;
}
__device__ __forceinline__ ull fmul2(ull a, ull b) {
    ull d; asm("mul.rn.f32x2 %0,%1,%2;" : "=l"(d) : "l"(a), "l"(b)); return d;
}
__device__ __forceinline__ void red_add_v2(float* p, float a, float b) {
    asm volatile("red.global.add.v2.f32 [%0], {%1,%2};"
                 :: "l"(p), "f"(a), "f"(b) : "memory");
}
__device__ __forceinline__ ull shfl_xor_u64(ull v, int mask) {
    uint lo = (uint)v, hi = (uint)(v >> 32);
    lo = __shfl_xor_sync(0xffffffffu, lo, mask);
    hi = __shfl_xor_sync(0xffffffffu, hi, mask);
    return ((ull)hi << 32) | lo;
}

// ---------------------------------------------------------------------------
// Fused: per-relation weights + zero g_hist/g_done + zero g_h1.
// ---------------------------------------------------------------------------
__global__ void compute_w_kernel(const float* __restrict__ comps1,
                                 const float* __restrict__ bases1,
                                 const float* __restrict__ comps2,
                                 const float* __restrict__ bases2) {
    int idx = blockIdx.x * blockDim.x + threadIdx.x;
    const int total1 = R_REL * F_DIM * E_DIM;
    const int total2 = R_REL * E_DIM * C_DIM;
    if (idx < total1) {
        int r = idx / (F_DIM * E_DIM);
        int fe = idx - r * (F_DIM * E_DIM);
        float acc = 0.f;
#pragma unroll
        for (int b = 0; b < B_BASES; b++)
            acc = fmaf(comps1[r * B_BASES + b], bases1[b * (F_DIM * E_DIM) + fe], acc);
        g_w1[idx] = acc;
    }
    if (idx < total2) {
        int r = idx / (E_DIM * C_DIM);
        int hc = idx - r * (E_DIM * C_DIM);
        float acc = 0.f;
#pragma unroll
        for (int b = 0; b < B_BASES; b++)
            acc = fmaf(comps2[r * B_BASES + b], bases2[b * (E_DIM * C_DIM) + hc], acc);
        g_w2[idx] = acc;
    }
    if (idx < R_REL) g_hist[idx] = 0;
    if (idx == 0) g_done = 0;
    float4* h4 = (float4*)g_h1;
    const int nh4 = N_NODES * E_DIM / 4;
    for (int i = idx; i < nh4; i += gridDim.x * blockDim.x)
        h4[i] = make_float4(0.f, 0.f, 0.f, 0.f);
}

// ---------------------------------------------------------------------------
// Fused: histogram + (last block) exclusive-scan -> g_cursor + out = bias2.
// ---------------------------------------------------------------------------
__global__ void hist_kernel(const int* __restrict__ rows, int nnz,
                            float* __restrict__ out,
                            const float* __restrict__ bias2) {
    __shared__ unsigned sh[R_REL];
    if (threadIdx.x < R_REL) sh[threadIdx.x] = 0;
    __syncthreads();
    int gsz = gridDim.x * blockDim.x;
    for (int e = blockIdx.x * blockDim.x + threadIdx.x; e < nnz; e += gsz)
        atomicAdd(&sh[(unsigned)rows[e] / N_NODES], 1u);
    for (int i = blockIdx.x * blockDim.x + threadIdx.x; i < N_NODES * C_DIM; i += gsz)
        out[i] = bias2[i & (C_DIM - 1)];
    __syncthreads();
    if (threadIdx.x < R_REL) atomicAdd(&g_hist[threadIdx.x], sh[threadIdx.x]);
    __threadfence();
    __syncthreads();
    if (threadIdx.x == 0) {
        unsigned t = atomicAdd(&g_done, 1u);
        if (t == gridDim.x - 1) {
            unsigned s = 0;
            for (int r = 0; r < R_REL; r++) { g_cursor[r] = s; s += g_hist[r]; }
        }
    }
}

// Block-aggregated scatter into relation buckets.
// After this kernel, g_cursor[r] == end offset of bucket r (prefix-inclusive).
#define SCATTER_CHUNK 8192
__global__ void scatter_kernel(const int* __restrict__ rows,
                               const int* __restrict__ cols,
                               const float* __restrict__ vals, int nnz) {
    __shared__ unsigned cnt[R_REL];
    __shared__ unsigned base[R_REL];
    int start = blockIdx.x * SCATTER_CHUNK;
    if (start >= nnz) return;
    int end = min(start + SCATTER_CHUNK, nnz);

    if (threadIdx.x < R_REL) cnt[threadIdx.x] = 0;
    __syncthreads();
    for (int e = start + threadIdx.x; e < end; e += blockDim.x)
        atomicAdd(&cnt[(unsigned)rows[e] / N_NODES], 1u);
    __syncthreads();
    if (threadIdx.x < R_REL) {
        base[threadIdx.x] = atomicAdd(&g_cursor[threadIdx.x], cnt[threadIdx.x]);
        cnt[threadIdx.x] = 0;
    }
    __syncthreads();
    for (int e = start + threadIdx.x; e < end; e += blockDim.x) {
        unsigned row = (unsigned)rows[e];
        unsigned r = row / N_NODES;
        unsigned n = row - r * N_NODES;
        unsigned pos = base[r] + atomicAdd(&cnt[r], 1u);
        g_nm[pos] = (n << 16) | (unsigned)cols[e];
        g_v[pos]  = vals[e];
    }
}

__global__ void relu_bias_kernel(const float* __restrict__ bias1) {
    int idx = blockIdx.x * blockDim.x + threadIdx.x;
    const int n4 = N_NODES * E_DIM / 4;
    if (idx < n4) {
        float4* h4 = (float4*)g_h1;
        const float4* b4 = (const float4*)bias1;
        float4 v = h4[idx];
        float4 b = b4[idx & (E_DIM / 4 - 1)];
        v.x = fmaxf(v.x + b.x, 0.f);
        v.y = fmaxf(v.y + b.y, 0.f);
        v.z = fmaxf(v.z + b.z, 0.f);
        v.w = fmaxf(v.w + b.w, 0.f);
        h4[idx] = v;
    }
}

// ---------------------------------------------------------------------------
// Layer 1: CTA = (relation, chunk); weights in registers; WARP PER EDGE.
// fi = lane>>4 (f-half), ep = lane&15 (e-pair: e = 2*ep, 2*ep+1).
// Lane w slice: 16 ull = w1[r][fi*16+ff][2*ep .. 2*ep+1].
// Whole warp reads ONE x row (coalesced, 1 line); shfl_xor(16) reduces fi;
// fi==0 lanes (16) do a contiguous 128B red.v2 scatter. Next edge's x is
// prefetched before the FFMA chain (double buffer).
// ---------------------------------------------------------------------------
__global__ __launch_bounds__(256)
void layer1_kernel(const float* __restrict__ x) {
    const unsigned r     = blockIdx.x / CHUNKS;
    const unsigned chunk = blockIdx.x % CHUNKS;
    const unsigned lo  = (r == 0) ? 0u : g_cursor[r - 1];
    const unsigned hi  = g_cursor[r];
    const unsigned len = hi - lo;
    const unsigned cstart = lo + (unsigned)(((ull)len * chunk) / CHUNKS);
    const unsigned cend   = lo + (unsigned)(((ull)len * (chunk + 1)) / CHUNKS);

    const int lane = threadIdx.x & 31;
    const int wid  = threadIdx.x >> 5;            // 8 warps / CTA
    const int fi   = lane >> 4;                   // 0/1
    const int ep   = lane & 15;                   // e-pair index

    const float* wb = g_w1 + r * (F_DIM * E_DIM) + (fi * 16) * E_DIM + ep * 2;
    ull w[16];
#pragma unroll
    for (int ff = 0; ff < 16; ff++)
        w[ff] = *(const ull*)(wb + ff * E_DIM);

    unsigned e = cstart + wid;
    if (e >= cend) return;

    // prologue: edge e
    unsigned nm = g_nm[e];
    float v = g_v[e];
    const float4* xp = (const float4*)(x + (size_t)(nm & 0xFFFFu) * F_DIM + fi * 16);
    float4 c0 = xp[0], c1 = xp[1], c2 = xp[2], c3 = xp[3];

    while (e < cend) {
        // prefetch next edge (clamped; overlaps the FFMA chain below)
        unsigned en = e + 8;
        unsigned pe = en < cend ? en : e;
        unsigned nm_n = g_nm[pe];
        float    v_n  = g_v[pe];
        const float4* xn = (const float4*)(x + (size_t)(nm_n & 0xFFFFu) * F_DIM + fi * 16);
        float4 n0 = xn[0], n1 = xn[1], n2 = xn[2], n3 = xn[3];

        float xs[16] = { c0.x, c0.y, c0.z, c0.w, c1.x, c1.y, c1.z, c1.w,
                         c2.x, c2.y, c2.z, c2.w, c3.x, c3.y, c3.z, c3.w };
        ull a0 = 0, a1 = 0;
#pragma unroll
        for (int ff = 0; ff < 16; ff += 2) {
            a0 = ffma2(pack2(xs[ff],     xs[ff]),     w[ff],     a0);
            a1 = ffma2(pack2(xs[ff + 1], xs[ff + 1]), w[ff + 1], a1);
        }
        ull a = fadd2(a0, a1);
        a = fadd2(a, shfl_xor_u64(a, 16));          // reduce over fi
        if (fi == 0) {
            float o0, o1;
            unpack2(fmul2(a, pack2(v, v)), o0, o1);
            red_add_v2(g_h1 + (size_t)(nm >> 16) * E_DIM + ep * 2, o0, o1);
        }
        e = en; nm = nm_n; v = v_n;
        c0 = n0; c1 = n1; c2 = n2; c3 = n3;
    }
}

// ---------------------------------------------------------------------------
// Layer 2: 2 edges per warp (16 lanes each). half = lane>>4 picks edge.
// fi = (lane>>3)&1 (f-half), cp = lane&7 (c-pair). Lane w slice: 16 ull.
// shfl_xor(8) reduces fi; fi==0 lanes do 64B-contiguous red.v2 per edge.
// ---------------------------------------------------------------------------
__global__ __launch_bounds__(256)
void layer2_kernel(float* __restrict__ out) {
    const unsigned r     = blockIdx.x / CHUNKS;
    const unsigned chunk = blockIdx.x % CHUNKS;
    const unsigned lo  = (r == 0) ? 0u : g_cursor[r - 1];
    const unsigned hi  = g_cursor[r];
    const unsigned len = hi - lo;
    const unsigned cstart = lo + (unsigned)(((ull)len * chunk) / CHUNKS);
    const unsigned cend   = lo + (unsigned)(((ull)len * (chunk + 1)) / CHUNKS);

    const int lane = threadIdx.x & 31;
    const int wid  = threadIdx.x >> 5;
    const int half = lane >> 4;                   // which edge of the pair
    const int fi   = (lane >> 3) & 1;
    const int cp   = lane & 7;                    // c-pair index

    const float* wb = g_w2 + r * (E_DIM * C_DIM) + (fi * 16) * C_DIM + cp * 2;
    ull w[16];
#pragma unroll
    for (int ff = 0; ff < 16; ff++)
        w[ff] = *(const ull*)(wb + ff * C_DIM);

    unsigned b = cstart + wid * 2;
    if (b >= cend) return;

    // prologue
    unsigned eIdx = b + half;
    unsigned ce = eIdx < cend ? eIdx : cend - 1;
    unsigned nm = g_nm[ce];
    float v = (eIdx < cend) ? g_v[ce] : 0.f;
    const float4* hp = (const float4*)(g_h1 + (size_t)(nm & 0xFFFFu) * E_DIM + fi * 16);
    float4 c0 = hp[0], c1 = hp[1], c2 = hp[2], c3 = hp[3];

    while (b < cend) {
        unsigned bn = b + 16;                      // 8 warps * 2 edges
        unsigned eN = bn + half;
        unsigned pe = eN < cend ? eN : ce;
        unsigned nm_n = g_nm[pe];
        float    v_n  = (bn < cend && eN < cend) ? g_v[pe] : 0.f;
        const float4* hn = (const float4*)(g_h1 + (size_t)(nm_n & 0xFFFFu) * E_DIM + fi * 16);
        float4 n0 = hn[0], n1 = hn[1], n2 = hn[2], n3 = hn[3];

        float xs[16] = { c0.x, c0.y, c0.z, c0.w, c1.x, c1.y, c1.z, c1.w,
                         c2.x, c2.y, c2.z, c2.w, c3.x, c3.y, c3.z, c3.w };
        ull a0 = 0, a1 = 0;
#pragma unroll
        for (int ff = 0; ff < 16; ff += 2) {
            a0 = ffma2(pack2(xs[ff],     xs[ff]),     w[ff],     a0);
            a1 = ffma2(pack2(xs[ff + 1], xs[ff + 1]), w[ff + 1], a1);
        }
        ull a = fadd2(a0, a1);
        a = fadd2(a, shfl_xor_u64(a, 8));           // reduce over fi
        if (fi == 0) {
            float o0, o1;
            unpack2(fmul2(a, pack2(v, v)), o0, o1);
            red_add_v2(out + (size_t)(nm >> 16) * C_DIM + cp * 2, o0, o1);
        }
        b = bn; ce = pe; nm = nm_n; v = v_n;
        c0 = n0; c1 = n1; c2 = n2; c3 = n3;
    }
}

// ---------------------------------------------------------------------------
extern "C" void kernel_launch(void* const* d_in, const int* in_sizes, int n_in,
                              void* d_out, int out_size) {
    const float* features = (const float*)d_in[0];
    const float* vals     = (const float*)d_in[1];
    const float* comps1   = (const float*)d_in[2];
    const float* bases1   = (const float*)d_in[3];
    const float* bias1    = (const float*)d_in[4];
    const float* comps2   = (const float*)d_in[5];
    const float* bases2   = (const float*)d_in[6];
    const float* bias2    = (const float*)d_in[7];
    const int*   rows     = (const int*)d_in[8];
    const int*   cols     = (const int*)d_in[9];
    float*       out      = (float*)d_out;
    const int    nnz      = in_sizes[8];

    // 1. weights + zero hist/done/h1
    compute_w_kernel<<<512, 256>>>(comps1, bases1, comps2, bases2);
    // 2. histogram + last-block scan + out=bias2
    hist_kernel<<<256, 256>>>(rows, nnz, out, bias2);
    // 3. bucket scatter (relation-sorted edge list; g_cursor -> bucket ends)
    scatter_kernel<<<(nnz + SCATTER_CHUNK - 1) / SCATTER_CHUNK, 512>>>(
        rows, cols, vals, nnz);
    // 4. layer 1 (register weights, warp-per-edge, prefetch pipeline)
    layer1_kernel<<<R_REL * CHUNKS, 256>>>(features);
    // 5. bias + relu
    relu_bias_kernel<<<(N_NODES * E_DIM / 4 + 255) / 256, 256>>>(bias1);
    // 6. layer 2
    layer2_kernel<<<R_REL * CHUNKS, 256>>>(out);
}

// round 11
// speedup vs baseline: 1.4727x; 1.1138x over previous
#include <cuda_runtime.h>

#define N_NODES 50000
#define R_REL 51
#define F_DIM 32
#define E_DIM 32
#define C_DIM 16
#define B_BASES 30
#define NNZ_MAX 2001024
#define CHUNKS 16           // chunks per relation bucket for layer kernels

typedef unsigned long long ull;
typedef unsigned int uint;

// ---- scratch (__device__ globals: no allocation allowed) -------------------
__device__ float g_w1[R_REL * F_DIM * E_DIM];            // [r][f][e]  208 KB
__device__ float g_w2[R_REL * E_DIM * C_DIM];            // [r][h][c]  104 KB
__device__ __align__(16) float g_h1[N_NODES * E_DIM];    // 6.4 MB
__device__ unsigned g_hist[R_REL];
__device__ unsigned g_cursor[R_REL];   // post-scatter: inclusive prefix end of bucket r
__device__ unsigned g_done;
__device__ __align__(16) unsigned g_nm[NNZ_MAX];         // (n<<16)|m (both <65536)
__device__ __align__(16) float    g_v[NNZ_MAX];

// ---- packed f32x2 helpers --------------------------------------------------
__device__ __forceinline__ ull pack2(float lo, float hi) {
    ull r; asm("mov.b64 %0,{%1,%2};" : "=l"(r) : "f"(lo), "f"(hi)); return r;
}
__device__ __forceinline__ void unpack2(ull v, float& lo, float& hi) {
    asm("mov.b64 {%0,%1},%2;" : "=f"(lo), "=f"(hi) : "l"(v));
}
__device__ __forceinline__ ull ffma2(ull a, ull b, ull c) {
    ull d; asm("fma.rn.f32x2 %0,%1,%2,%3;" : "=l"(d) : "l"(a), "l"(b), "l"(c)); return d;
}
__device__ __forceinline__ ull fadd2(ull a, ull b) {
    ull d; asm("add.rn.f32x2 %0,%1,%2;" : "=l"(d) : "l"(a), "l"(b)); return d;
}
__device__ __forceinline__ ull fmul2(ull a, ull b) {
    ull d; asm("mul.rn.f32x2 %0,%1,%2;" : "=l"(d) : "l"(a), "l"(b)); return d;
}
__device__ __forceinline__ void red_add_v2(float* p, float a, float b) {
    asm volatile("red.global.add.v2.f32 [%0], {%1,%2};"
                 :: "l"(p), "f"(a), "f"(b) : "memory");
}
__device__ __forceinline__ ull shfl_xor_u64(ull v, int mask) {
    uint lo = (uint)v, hi = (uint)(v >> 32);
    lo = __shfl_xor_sync(0xffffffffu, lo, mask);
    hi = __shfl_xor_sync(0xffffffffu, hi, mask);
    return ((ull)hi << 32) | lo;
}

// ---------------------------------------------------------------------------
// Fused: per-relation weights + zero g_hist/g_done + zero g_h1.
// ---------------------------------------------------------------------------
__global__ void compute_w_kernel(const float* __restrict__ comps1,
                                 const float* __restrict__ bases1,
                                 const float* __restrict__ comps2,
                                 const float* __restrict__ bases2) {
    int idx = blockIdx.x * blockDim.x + threadIdx.x;
    const int total1 = R_REL * F_DIM * E_DIM;
    const int total2 = R_REL * E_DIM * C_DIM;
    if (idx < total1) {
        int r = idx / (F_DIM * E_DIM);
        int fe = idx - r * (F_DIM * E_DIM);
        float acc = 0.f;
#pragma unroll
        for (int b = 0; b < B_BASES; b++)
            acc = fmaf(comps1[r * B_BASES + b], bases1[b * (F_DIM * E_DIM) + fe], acc);
        g_w1[idx] = acc;
    }
    if (idx < total2) {
        int r = idx / (E_DIM * C_DIM);
        int hc = idx - r * (E_DIM * C_DIM);
        float acc = 0.f;
#pragma unroll
        for (int b = 0; b < B_BASES; b++)
            acc = fmaf(comps2[r * B_BASES + b], bases2[b * (E_DIM * C_DIM) + hc], acc);
        g_w2[idx] = acc;
    }
    if (idx < R_REL) g_hist[idx] = 0;
    if (idx == 0) g_done = 0;
    float4* h4 = (float4*)g_h1;
    const int nh4 = N_NODES * E_DIM / 4;
    for (int i = idx; i < nh4; i += gridDim.x * blockDim.x)
        h4[i] = make_float4(0.f, 0.f, 0.f, 0.f);
}

// ---------------------------------------------------------------------------
// Fused: histogram + (last block) exclusive-scan -> g_cursor + out = bias2.
// ---------------------------------------------------------------------------
__global__ void hist_kernel(const int* __restrict__ rows, int nnz,
                            float* __restrict__ out,
                            const float* __restrict__ bias2) {
    __shared__ unsigned sh[R_REL];
    if (threadIdx.x < R_REL) sh[threadIdx.x] = 0;
    __syncthreads();
    int gsz = gridDim.x * blockDim.x;
    for (int e = blockIdx.x * blockDim.x + threadIdx.x; e < nnz; e += gsz)
        atomicAdd(&sh[(unsigned)rows[e] / N_NODES], 1u);
    for (int i = blockIdx.x * blockDim.x + threadIdx.x; i < N_NODES * C_DIM; i += gsz)
        out[i] = bias2[i & (C_DIM - 1)];
    __syncthreads();
    if (threadIdx.x < R_REL) atomicAdd(&g_hist[threadIdx.x], sh[threadIdx.x]);
    __threadfence();
    __syncthreads();
    if (threadIdx.x == 0) {
        unsigned t = atomicAdd(&g_done, 1u);
        if (t == gridDim.x - 1) {
            unsigned s = 0;
            for (int r = 0; r < R_REL; r++) { g_cursor[r] = s; s += g_hist[r]; }
        }
    }
}

// Block-aggregated scatter into relation buckets.
// After this kernel, g_cursor[r] == end offset of bucket r (prefix-inclusive).
#define SCATTER_CHUNK 8192
__global__ void scatter_kernel(const int* __restrict__ rows,
                               const int* __restrict__ cols,
                               const float* __restrict__ vals, int nnz) {
    __shared__ unsigned cnt[R_REL];
    __shared__ unsigned base[R_REL];
    int start = blockIdx.x * SCATTER_CHUNK;
    if (start >= nnz) return;
    int end = min(start + SCATTER_CHUNK, nnz);

    if (threadIdx.x < R_REL) cnt[threadIdx.x] = 0;
    __syncthreads();
    for (int e = start + threadIdx.x; e < end; e += blockDim.x)
        atomicAdd(&cnt[(unsigned)rows[e] / N_NODES], 1u);
    __syncthreads();
    if (threadIdx.x < R_REL) {
        base[threadIdx.x] = atomicAdd(&g_cursor[threadIdx.x], cnt[threadIdx.x]);
        cnt[threadIdx.x] = 0;
    }
    __syncthreads();
    for (int e = start + threadIdx.x; e < end; e += blockDim.x) {
        unsigned row = (unsigned)rows[e];
        unsigned r = row / N_NODES;
        unsigned n = row - r * N_NODES;
        unsigned pos = base[r] + atomicAdd(&cnt[r], 1u);
        g_nm[pos] = (n << 16) | (unsigned)cols[e];
        g_v[pos]  = vals[e];
    }
}

__global__ void relu_bias_kernel(const float* __restrict__ bias1) {
    int idx = blockIdx.x * blockDim.x + threadIdx.x;
    const int n4 = N_NODES * E_DIM / 4;
    if (idx < n4) {
        float4* h4 = (float4*)g_h1;
        const float4* b4 = (const float4*)bias1;
        float4 v = h4[idx];
        float4 b = b4[idx & (E_DIM / 4 - 1)];
        v.x = fmaxf(v.x + b.x, 0.f);
        v.y = fmaxf(v.y + b.y, 0.f);
        v.z = fmaxf(v.z + b.z, 0.f);
        v.w = fmaxf(v.w + b.w, 0.f);
        h4[idx] = v;
    }
}

// ---------------------------------------------------------------------------
// Layer 1: CTA = (relation, chunk); register weights; warp-per-edge.
// fi = lane>>4 (f-half), ep = lane&15 (e-pair: e0=2ep, e1=2ep+1).
// f32x2 halves carry (f even, f odd) contributions to the SAME e:
//   x row reinterpreted as ulonglong2 = packed (x[2k],x[2k+1]) -> used directly,
//   weights pre-packed across f: wA[k]=(w[2k][e0],w[2k+1][e0]), wB for e1.
// Zero pack instructions in the hot loop. Epilogue folds lo+hi, shfl over fi,
// contiguous red.v2 scatter. Next edge prefetched over the FFMA chain.
// ---------------------------------------------------------------------------
__global__ __launch_bounds__(256, 3)
void layer1_kernel(const float* __restrict__ x) {
    const unsigned r     = blockIdx.x / CHUNKS;
    const unsigned chunk = blockIdx.x % CHUNKS;
    const unsigned lo  = (r == 0) ? 0u : g_cursor[r - 1];
    const unsigned hi  = g_cursor[r];
    const unsigned len = hi - lo;
    const unsigned cstart = lo + (unsigned)(((ull)len * chunk) / CHUNKS);
    const unsigned cend   = lo + (unsigned)(((ull)len * (chunk + 1)) / CHUNKS);

    const int lane = threadIdx.x & 31;
    const int wid  = threadIdx.x >> 5;            // 8 warps / CTA
    const int fi   = lane >> 4;                   // 0/1 (f half)
    const int ep   = lane & 15;                   // e-pair index

    // Pre-pack weights across f (one-time).
    const float* wr = g_w1 + r * (F_DIM * E_DIM) + (fi * 16) * E_DIM;
    ull wA[8], wB[8];
#pragma unroll
    for (int k = 0; k < 8; k++) {
        wA[k] = pack2(wr[(2 * k) * E_DIM + 2 * ep],
                      wr[(2 * k + 1) * E_DIM + 2 * ep]);
        wB[k] = pack2(wr[(2 * k) * E_DIM + 2 * ep + 1],
                      wr[(2 * k + 1) * E_DIM + 2 * ep + 1]);
    }

    unsigned e = cstart + wid;
    if (e >= cend) return;

    // prologue: edge e
    unsigned nm = g_nm[e];
    float v = g_v[e];
    {
    const ulonglong2* xp =
        (const ulonglong2*)(x + (size_t)(nm & 0xFFFFu) * F_DIM + fi * 16);
    ulonglong2 c0 = xp[0], c1 = xp[1], c2 = xp[2], c3 = xp[3];

    while (e < cend) {
        // prefetch next edge (clamped; overlaps the FFMA chain below)
        unsigned en = e + 8;
        unsigned pe = en < cend ? en : e;
        unsigned nm_n = g_nm[pe];
        float    v_n  = g_v[pe];
        const ulonglong2* xn =
            (const ulonglong2*)(x + (size_t)(nm_n & 0xFFFFu) * F_DIM + fi * 16);
        ulonglong2 n0 = xn[0], n1 = xn[1], n2 = xn[2], n3 = xn[3];

        ull accA = 0, accB = 0;       // halves = (f-even, f-odd) partials
        accA = ffma2(c0.x, wA[0], accA);  accB = ffma2(c0.x, wB[0], accB);
        accA = ffma2(c0.y, wA[1], accA);  accB = ffma2(c0.y, wB[1], accB);
        accA = ffma2(c1.x, wA[2], accA);  accB = ffma2(c1.x, wB[2], accB);
        accA = ffma2(c1.y, wA[3], accA);  accB = ffma2(c1.y, wB[3], accB);
        accA = ffma2(c2.x, wA[4], accA);  accB = ffma2(c2.x, wB[4], accB);
        accA = ffma2(c2.y, wA[5], accA);  accB = ffma2(c2.y, wB[5], accB);
        accA = ffma2(c3.x, wA[6], accA);  accB = ffma2(c3.x, wB[6], accB);
        accA = ffma2(c3.y, wA[7], accA);  accB = ffma2(c3.y, wB[7], accB);

        float aLo, aHi, bLo, bHi;
        unpack2(accA, aLo, aHi);
        unpack2(accB, bLo, bHi);
        ull p = pack2(aLo + aHi, bLo + bHi);      // (e0, e1) partial for this fi
        p = fadd2(p, shfl_xor_u64(p, 16));        // reduce over fi
        if (fi == 0) {
            float o0, o1;
            unpack2(fmul2(p, pack2(v, v)), o0, o1);
            red_add_v2(g_h1 + (size_t)(nm >> 16) * E_DIM + ep * 2, o0, o1);
        }
        e = en; nm = nm_n; v = v_n;
        c0 = n0; c1 = n1; c2 = n2; c3 = n3;
    }
    }
}

// ---------------------------------------------------------------------------
// Layer 2: 2 edges per warp (16 lanes each): half = lane>>4 picks edge.
// fi = (lane>>3)&1 (f-half), cp = lane&7 (c-pair: c0=2cp, c1=2cp+1).
// Same f-packed accumulation scheme; shfl_xor(8) reduces fi; red.v2 scatter.
// ---------------------------------------------------------------------------
__global__ __launch_bounds__(256, 3)
void layer2_kernel(float* __restrict__ out) {
    const unsigned r     = blockIdx.x / CHUNKS;
    const unsigned chunk = blockIdx.x % CHUNKS;
    const unsigned lo  = (r == 0) ? 0u : g_cursor[r - 1];
    const unsigned hi  = g_cursor[r];
    const unsigned len = hi - lo;
    const unsigned cstart = lo + (unsigned)(((ull)len * chunk) / CHUNKS);
    const unsigned cend   = lo + (unsigned)(((ull)len * (chunk + 1)) / CHUNKS);

    const int lane = threadIdx.x & 31;
    const int wid  = threadIdx.x >> 5;
    const int half = lane >> 4;                   // which edge of the pair
    const int fi   = (lane >> 3) & 1;             // f half
    const int cp   = lane & 7;                    // c-pair index

    const float* wr = g_w2 + r * (E_DIM * C_DIM) + (fi * 16) * C_DIM;
    ull wA[8], wB[8];
#pragma unroll
    for (int k = 0; k < 8; k++) {
        wA[k] = pack2(wr[(2 * k) * C_DIM + 2 * cp],
                      wr[(2 * k + 1) * C_DIM + 2 * cp]);
        wB[k] = pack2(wr[(2 * k) * C_DIM + 2 * cp + 1],
                      wr[(2 * k + 1) * C_DIM + 2 * cp + 1]);
    }

    unsigned b = cstart + wid * 2;
    if (b >= cend) return;

    // prologue
    unsigned eIdx = b + half;
    unsigned ce = eIdx < cend ? eIdx : cend - 1;
    unsigned nm = g_nm[ce];
    float v = (eIdx < cend) ? g_v[ce] : 0.f;
    const ulonglong2* hp =
        (const ulonglong2*)(g_h1 + (size_t)(nm & 0xFFFFu) * E_DIM + fi * 16);
    ulonglong2 c0 = hp[0], c1 = hp[1], c2 = hp[2], c3 = hp[3];

    while (b < cend) {
        unsigned bn = b + 16;                     // 8 warps * 2 edges
        unsigned eN = bn + half;
        unsigned pe = eN < cend ? eN : ce;
        unsigned nm_n = g_nm[pe];
        float    v_n  = (eN < cend) ? g_v[pe] : 0.f;
        const ulonglong2* hn =
            (const ulonglong2*)(g_h1 + (size_t)(nm_n & 0xFFFFu) * E_DIM + fi * 16);
        ulonglong2 n0 = hn[0], n1 = hn[1], n2 = hn[2], n3 = hn[3];

        ull accA = 0, accB = 0;
        accA = ffma2(c0.x, wA[0], accA);  accB = ffma2(c0.x, wB[0], accB);
        accA = ffma2(c0.y, wA[1], accA);  accB = ffma2(c0.y, wB[1], accB);
        accA = ffma2(c1.x, wA[2], accA);  accB = ffma2(c1.x, wB[2], accB);
        accA = ffma2(c1.y, wA[3], accA);  accB = ffma2(c1.y, wB[3], accB);
        accA = ffma2(c2.x, wA[4], accA);  accB = ffma2(c2.x, wB[4], accB);
        accA = ffma2(c2.y, wA[5], accA);  accB = ffma2(c2.y, wB[5], accB);
        accA = ffma2(c3.x, wA[6], accA);  accB = ffma2(c3.x, wB[6], accB);
        accA = ffma2(c3.y, wA[7], accA);  accB = ffma2(c3.y, wB[7], accB);

        float aLo, aHi, bLo, bHi;
        unpack2(accA, aLo, aHi);
        unpack2(accB, bLo, bHi);
        ull p = pack2(aLo + aHi, bLo + bHi);      // (c0, c1) partial for this fi
        p = fadd2(p, shfl_xor_u64(p, 8));         // reduce over fi
        if (fi == 0) {
            float o0, o1;
            unpack2(fmul2(p, pack2(v, v)), o0, o1);
            red_add_v2(out + (size_t)(nm >> 16) * C_DIM + cp * 2, o0, o1);
        }
        b = bn; ce = pe; nm = nm_n; v = v_n;
        c0 = n0; c1 = n1; c2 = n2; c3 = n3;
    }
}

// ---------------------------------------------------------------------------
extern "C" void kernel_launch(void* const* d_in, const int* in_sizes, int n_in,
                              void* d_out, int out_size) {
    const float* features = (const float*)d_in[0];
    const float* vals     = (const float*)d_in[1];
    const float* comps1   = (const float*)d_in[2];
    const float* bases1   = (const float*)d_in[3];
    const float* bias1    = (const float*)d_in[4];
    const float* comps2   = (const float*)d_in[5];
    const float* bases2   = (const float*)d_in[6];
    const float* bias2    = (const float*)d_in[7];
    const int*   rows     = (const int*)d_in[8];
    const int*   cols     = (const int*)d_in[9];
    float*       out      = (float*)d_out;
    const int    nnz      = in_sizes[8];

    // 1. weights + zero hist/done/h1
    compute_w_kernel<<<512, 256>>>(comps1, bases1, comps2, bases2);
    // 2. histogram + last-block scan + out=bias2
    hist_kernel<<<256, 256>>>(rows, nnz, out, bias2);
    // 3. bucket scatter (relation-sorted edge list; g_cursor -> bucket ends)
    scatter_kernel<<<(nnz + SCATTER_CHUNK - 1) / SCATTER_CHUNK, 512>>>(
        rows, cols, vals, nnz);
    // 4. layer 1 (register weights, warp-per-edge, f-packed FFMA2, prefetch)
    layer1_kernel<<<R_REL * CHUNKS, 256>>>(features);
    // 5. bias + relu
    relu_bias_kernel<<<(N_NODES * E_DIM / 4 + 255) / 256, 256>>>(bias1);
    // 6. layer 2
    layer2_kernel<<<R_REL * CHUNKS, 256>>>(out);
}

// round 12
// speedup vs baseline: 1.6633x; 1.1294x over previous
#include <cuda_runtime.h>

#define N_NODES 50000
#define R_REL 51
#define F_DIM 32
#define E_DIM 32
#define C_DIM 16
#define B_BASES 30
#define NNZ_MAX 2001024
#define CHUNKS 32           // chunks per relation bucket for layer kernels

typedef unsigned long long ull;
typedef unsigned int uint;

// ---- scratch (__device__ globals: no allocation allowed) -------------------
__device__ float g_w1[R_REL * F_DIM * E_DIM];            // [r][f][e]  208 KB
__device__ float g_w2[R_REL * E_DIM * C_DIM];            // [r][h][c]  104 KB
__device__ __align__(16) float g_h1[N_NODES * E_DIM];    // 6.4 MB
__device__ unsigned g_hist[R_REL];
__device__ unsigned g_cursor[R_REL];   // post-scatter: inclusive prefix end of bucket r
__device__ unsigned g_done;
__device__ __align__(16) unsigned g_nm[NNZ_MAX];         // (n<<16)|m (both <65536)
__device__ __align__(16) float    g_v[NNZ_MAX];

// ---- packed f32x2 helpers --------------------------------------------------
__device__ __forceinline__ ull pack2(float lo, float hi) {
    ull r; asm("mov.b64 %0,{%1,%2};" : "=l"(r) : "f"(lo), "f"(hi)); return r;
}
__device__ __forceinline__ void unpack2(ull v, float& lo, float& hi) {
    asm("mov.b64 {%0,%1},%2;" : "=f"(lo), "=f"(hi) : "l"(v));
}
__device__ __forceinline__ ull ffma2(ull a, ull b, ull c) {
    ull d; asm("fma.rn.f32x2 %0,%1,%2,%3;" : "=l"(d) : "l"(a), "l"(b), "l"(c)); return d;
}
__device__ __forceinline__ ull fadd2(ull a, ull b) {
    ull d; asm("add.rn.f32x2 %0,%1,%2;" : "=l"(d) : "l"(a), "l"(b)); return d;
}
__device__ __forceinline__ ull fmul2(ull a, ull b) {
    ull d; asm("mul.rn.f32x2 %0,%1,%2;" : "=l"(d) : "l"(a), "l"(b)); return d;
}
__device__ __forceinline__ void red_add_v2(float* p, float a, float b) {
    asm volatile("red.global.add.v2.f32 [%0], {%1,%2};"
                 :: "l"(p), "f"(a), "f"(b) : "memory");
}
__device__ __forceinline__ ull shfl_xor_u64(ull v, int mask) {
    uint lo = (uint)v, hi = (uint)(v >> 32);
    lo = __shfl_xor_sync(0xffffffffu, lo, mask);
    hi = __shfl_xor_sync(0xffffffffu, hi, mask);
    return ((ull)hi << 32) | lo;
}
__device__ __forceinline__ ulonglong2 ldg_u64x2(const ulonglong2* p) {
    ulonglong2 q;
    asm("ld.global.nc.v2.u64 {%0,%1}, [%2];" : "=l"(q.x), "=l"(q.y) : "l"(p));
    return q;
}

// ---------------------------------------------------------------------------
// Fused: per-relation weights + zero g_hist/g_done + zero g_h1.
// ---------------------------------------------------------------------------
__global__ void compute_w_kernel(const float* __restrict__ comps1,
                                 const float* __restrict__ bases1,
                                 const float* __restrict__ comps2,
                                 const float* __restrict__ bases2) {
    int idx = blockIdx.x * blockDim.x + threadIdx.x;
    const int total1 = R_REL * F_DIM * E_DIM;
    const int total2 = R_REL * E_DIM * C_DIM;
    if (idx < total1) {
        int r = idx / (F_DIM * E_DIM);
        int fe = idx - r * (F_DIM * E_DIM);
        float acc = 0.f;
#pragma unroll
        for (int b = 0; b < B_BASES; b++)
            acc = fmaf(comps1[r * B_BASES + b], bases1[b * (F_DIM * E_DIM) + fe], acc);
        g_w1[idx] = acc;
    }
    if (idx < total2) {
        int r = idx / (E_DIM * C_DIM);
        int hc = idx - r * (E_DIM * C_DIM);
        float acc = 0.f;
#pragma unroll
        for (int b = 0; b < B_BASES; b++)
            acc = fmaf(comps2[r * B_BASES + b], bases2[b * (E_DIM * C_DIM) + hc], acc);
        g_w2[idx] = acc;
    }
    if (idx < R_REL) g_hist[idx] = 0;
    if (idx == 0) g_done = 0;
    float4* h4 = (float4*)g_h1;
    const int nh4 = N_NODES * E_DIM / 4;
    for (int i = idx; i < nh4; i += gridDim.x * blockDim.x)
        h4[i] = make_float4(0.f, 0.f, 0.f, 0.f);
}

// ---------------------------------------------------------------------------
// Fused: histogram + (last block) exclusive-scan -> g_cursor + out = bias2.
// ---------------------------------------------------------------------------
__global__ void hist_kernel(const int* __restrict__ rows, int nnz,
                            float* __restrict__ out,
                            const float* __restrict__ bias2) {
    __shared__ unsigned sh[R_REL];
    if (threadIdx.x < R_REL) sh[threadIdx.x] = 0;
    __syncthreads();
    int gsz = gridDim.x * blockDim.x;
    for (int e = blockIdx.x * blockDim.x + threadIdx.x; e < nnz; e += gsz)
        atomicAdd(&sh[(unsigned)rows[e] / N_NODES], 1u);
    for (int i = blockIdx.x * blockDim.x + threadIdx.x; i < N_NODES * C_DIM; i += gsz)
        out[i] = bias2[i & (C_DIM - 1)];
    __syncthreads();
    if (threadIdx.x < R_REL) atomicAdd(&g_hist[threadIdx.x], sh[threadIdx.x]);
    __threadfence();
    __syncthreads();
    if (threadIdx.x == 0) {
        unsigned t = atomicAdd(&g_done, 1u);
        if (t == gridDim.x - 1) {
            unsigned s = 0;
            for (int r = 0; r < R_REL; r++) { g_cursor[r] = s; s += g_hist[r]; }
        }
    }
}

// Block-aggregated scatter into relation buckets.
// After this kernel, g_cursor[r] == end offset of bucket r (prefix-inclusive).
#define SCATTER_CHUNK 8192
__global__ void scatter_kernel(const int* __restrict__ rows,
                               const int* __restrict__ cols,
                               const float* __restrict__ vals, int nnz) {
    __shared__ unsigned cnt[R_REL];
    __shared__ unsigned base[R_REL];
    int start = blockIdx.x * SCATTER_CHUNK;
    if (start >= nnz) return;
    int end = min(start + SCATTER_CHUNK, nnz);

    if (threadIdx.x < R_REL) cnt[threadIdx.x] = 0;
    __syncthreads();
    for (int e = start + threadIdx.x; e < end; e += blockDim.x)
        atomicAdd(&cnt[(unsigned)rows[e] / N_NODES], 1u);
    __syncthreads();
    if (threadIdx.x < R_REL) {
        base[threadIdx.x] = atomicAdd(&g_cursor[threadIdx.x], cnt[threadIdx.x]);
        cnt[threadIdx.x] = 0;
    }
    __syncthreads();
    for (int e = start + threadIdx.x; e < end; e += blockDim.x) {
        unsigned row = (unsigned)rows[e];
        unsigned r = row / N_NODES;
        unsigned n = row - r * N_NODES;
        unsigned pos = base[r] + atomicAdd(&cnt[r], 1u);
        g_nm[pos] = (n << 16) | (unsigned)cols[e];
        g_v[pos]  = vals[e];
    }
}

__global__ void relu_bias_kernel(const float* __restrict__ bias1) {
    int idx = blockIdx.x * blockDim.x + threadIdx.x;
    const int n4 = N_NODES * E_DIM / 4;
    if (idx < n4) {
        float4* h4 = (float4*)g_h1;
        const float4* b4 = (const float4*)bias1;
        float4 v = h4[idx];
        float4 b = b4[idx & (E_DIM / 4 - 1)];
        v.x = fmaxf(v.x + b.x, 0.f);
        v.y = fmaxf(v.y + b.y, 0.f);
        v.z = fmaxf(v.z + b.z, 0.f);
        v.w = fmaxf(v.w + b.w, 0.f);
        h4[idx] = v;
    }
}

// ---------------------------------------------------------------------------
// Layer 1: CTA = (relation, chunk); register weights; warp-per-edge.
// fi = lane>>4 (f-half), ep = lane&15 (e-pair: e0=2ep, e1=2ep+1).
// f32x2 halves carry (f even, f odd) partials to the SAME e (pack-free math).
// TWO-LEVEL pipeline: edge meta (nm,v) prefetched 2 ahead; x row 1 ahead.
// ---------------------------------------------------------------------------
__global__ __launch_bounds__(256, 3)
void layer1_kernel(const float* __restrict__ x) {
    const unsigned r     = blockIdx.x / CHUNKS;
    const unsigned chunk = blockIdx.x % CHUNKS;
    const unsigned lo  = (r == 0) ? 0u : g_cursor[r - 1];
    const unsigned hi  = g_cursor[r];
    const unsigned len = hi - lo;
    const unsigned cstart = lo + (unsigned)(((ull)len * chunk) / CHUNKS);
    const unsigned cend   = lo + (unsigned)(((ull)len * (chunk + 1)) / CHUNKS);

    const int lane = threadIdx.x & 31;
    const int wid  = threadIdx.x >> 5;            // 8 warps / CTA
    const int fi   = lane >> 4;                   // 0/1 (f half)
    const int ep   = lane & 15;                   // e-pair index

    // Pre-pack weights across f (one-time).
    const float* wr = g_w1 + r * (F_DIM * E_DIM) + (fi * 16) * E_DIM;
    ull wA[8], wB[8];
#pragma unroll
    for (int k = 0; k < 8; k++) {
        wA[k] = pack2(wr[(2 * k) * E_DIM + 2 * ep],
                      wr[(2 * k + 1) * E_DIM + 2 * ep]);
        wB[k] = pack2(wr[(2 * k) * E_DIM + 2 * ep + 1],
                      wr[(2 * k + 1) * E_DIM + 2 * ep + 1]);
    }

    unsigned e0 = cstart + wid;
    if (e0 >= cend) return;
    const unsigned last = cend - 1;

    // pipeline prologue: meta for e0 and e1; x row for e0
    unsigned e1 = e0 + 8;
    unsigned nm0 = g_nm[e0];
    float    v0  = g_v[e0];
    unsigned p1  = e1 < cend ? e1 : last;
    unsigned nm1 = g_nm[p1];
    float    v1  = g_v[p1];

    const ulonglong2* xp0 =
        (const ulonglong2*)(x + (size_t)(nm0 & 0xFFFFu) * F_DIM + fi * 16);
    ulonglong2 c0 = ldg_u64x2(xp0), c1 = ldg_u64x2(xp0 + 1);

    while (e0 < cend) {
        // level-2 prefetch: meta for e2
        unsigned e2 = e1 + 8;
        unsigned p2 = e2 < cend ? e2 : last;
        unsigned nm2 = g_nm[p2];
        float    v2  = g_v[p2];
        // level-1 prefetch: x row for e1 (meta already resident)
        const ulonglong2* xp1 =
            (const ulonglong2*)(x + (size_t)(nm1 & 0xFFFFu) * F_DIM + fi * 16);
        ulonglong2 n0 = ldg_u64x2(xp1), n1 = ldg_u64x2(xp1 + 1);

        ull accA = 0, accB = 0;       // halves = (f-even, f-odd) partials
        accA = ffma2(c0.x, wA[0], accA);  accB = ffma2(c0.x, wB[0], accB);
        accA = ffma2(c0.y, wA[1], accA);  accB = ffma2(c0.y, wB[1], accB);
        accA = ffma2(c1.x, wA[2], accA);  accB = ffma2(c1.x, wB[2], accB);
        accA = ffma2(c1.y, wA[3], accA);  accB = ffma2(c1.y, wB[3], accB);
        ulonglong2 c2 = ldg_u64x2(xp1 + 2), c3 = ldg_u64x2(xp0 + 2);
        // NOTE: c3 here reloads cur row's tail issued in prologue order below
        accA = ffma2(c3.x, wA[4], accA);  accB = ffma2(c3.x, wB[4], accB);
        accA = ffma2(c3.y, wA[5], accA);  accB = ffma2(c3.y, wB[5], accB);
        ulonglong2 c4 = ldg_u64x2(xp0 + 3), n3 = ldg_u64x2(xp1 + 3);
        accA = ffma2(c4.x, wA[6], accA);  accB = ffma2(c4.x, wB[6], accB);
        accA = ffma2(c4.y, wA[7], accA);  accB = ffma2(c4.y, wB[7], accB);

        float aLo, aHi, bLo, bHi;
        unpack2(accA, aLo, aHi);
        unpack2(accB, bLo, bHi);
        ull p = pack2(aLo + aHi, bLo + bHi);      // (e0, e1) partial for this fi
        p = fadd2(p, shfl_xor_u64(p, 16));        // reduce over fi
        if (fi == 0) {
            float o0, o1;
            unpack2(fmul2(p, pack2(v0, v0)), o0, o1);
            red_add_v2(g_h1 + (size_t)(nm0 >> 16) * E_DIM + ep * 2, o0, o1);
        }
        // shift pipeline
        e0 = e1; nm0 = nm1; v0 = v1;
        e1 = e2; nm1 = nm2; v1 = v2;
        c0 = n0; c1 = n1;
        xp0 = xp1;            // next iteration's "cur row tail" pointer
        (void)c2; (void)n3;
    }
}

// ---------------------------------------------------------------------------
// Layer 2: 2 edges per warp (16 lanes each): half = lane>>4 picks edge.
// fi = (lane>>3)&1 (f-half), cp = lane&7 (c-pair: c0=2cp, c1=2cp+1).
// Same pack-free math + two-level pipeline; shfl_xor(8) reduce; red.v2 scatter.
// ---------------------------------------------------------------------------
__global__ __launch_bounds__(256, 3)
void layer2_kernel(float* __restrict__ out) {
    const unsigned r     = blockIdx.x / CHUNKS;
    const unsigned chunk = blockIdx.x % CHUNKS;
    const unsigned lo  = (r == 0) ? 0u : g_cursor[r - 1];
    const unsigned hi  = g_cursor[r];
    const unsigned len = hi - lo;
    const unsigned cstart = lo + (unsigned)(((ull)len * chunk) / CHUNKS);
    const unsigned cend   = lo + (unsigned)(((ull)len * (chunk + 1)) / CHUNKS);

    const int lane = threadIdx.x & 31;
    const int wid  = threadIdx.x >> 5;
    const int half = lane >> 4;                   // which edge of the pair
    const int fi   = (lane >> 3) & 1;             // f half
    const int cp   = lane & 7;                    // c-pair index

    const float* wr = g_w2 + r * (E_DIM * C_DIM) + (fi * 16) * C_DIM;
    ull wA[8], wB[8];
#pragma unroll
    for (int k = 0; k < 8; k++) {
        wA[k] = pack2(wr[(2 * k) * C_DIM + 2 * cp],
                      wr[(2 * k + 1) * C_DIM + 2 * cp]);
        wB[k] = pack2(wr[(2 * k) * C_DIM + 2 * cp + 1],
                      wr[(2 * k + 1) * C_DIM + 2 * cp + 1]);
    }

    unsigned b0 = cstart + wid * 2;
    if (b0 >= cend) return;
    const unsigned last = cend - 1;

    // prologue
    unsigned eI0 = b0 + half;
    unsigned q0  = eI0 < cend ? eI0 : last;
    unsigned nm0 = g_nm[q0];
    float    v0  = (eI0 < cend) ? g_v[q0] : 0.f;

    unsigned b1 = b0 + 16;
    unsigned eI1 = b1 + half;
    unsigned q1  = eI1 < cend ? eI1 : last;
    unsigned nm1 = g_nm[q1];
    float    v1  = (eI1 < cend) ? g_v[q1] : 0.f;

    const ulonglong2* hp0 =
        (const ulonglong2*)(g_h1 + (size_t)(nm0 & 0xFFFFu) * E_DIM + fi * 16);
    ulonglong2 c0 = ldg_u64x2(hp0), c1 = ldg_u64x2(hp0 + 1);

    while (b0 < cend) {
        unsigned b2 = b1 + 16;
        unsigned eI2 = b2 + half;
        unsigned q2  = eI2 < cend ? eI2 : last;
        unsigned nm2 = g_nm[q2];
        float    v2  = (eI2 < cend) ? g_v[q2] : 0.f;

        const ulonglong2* hp1 =
            (const ulonglong2*)(g_h1 + (size_t)(nm1 & 0xFFFFu) * E_DIM + fi * 16);
        ulonglong2 n0 = ldg_u64x2(hp1), n1 = ldg_u64x2(hp1 + 1);

        ull accA = 0, accB = 0;
        accA = ffma2(c0.x, wA[0], accA);  accB = ffma2(c0.x, wB[0], accB);
        accA = ffma2(c0.y, wA[1], accA);  accB = ffma2(c0.y, wB[1], accB);
        accA = ffma2(c1.x, wA[2], accA);  accB = ffma2(c1.x, wB[2], accB);
        accA = ffma2(c1.y, wA[3], accA);  accB = ffma2(c1.y, wB[3], accB);
        ulonglong2 c2 = ldg_u64x2(hp0 + 2), c3 = ldg_u64x2(hp0 + 3);
        accA = ffma2(c2.x, wA[4], accA);  accB = ffma2(c2.x, wB[4], accB);
        accA = ffma2(c2.y, wA[5], accA);  accB = ffma2(c2.y, wB[5], accB);
        accA = ffma2(c3.x, wA[6], accA);  accB = ffma2(c3.x, wB[6], accB);
        accA = ffma2(c3.y, wA[7], accA);  accB = ffma2(c3.y, wB[7], accB);

        float aLo, aHi, bLo, bHi;
        unpack2(accA, aLo, aHi);
        unpack2(accB, bLo, bHi);
        ull p = pack2(aLo + aHi, bLo + bHi);
        p = fadd2(p, shfl_xor_u64(p, 8));
        if (fi == 0) {
            float o0, o1;
            unpack2(fmul2(p, pack2(v0, v0)), o0, o1);
            red_add_v2(out + (size_t)(nm0 >> 16) * C_DIM + cp * 2, o0, o1);
        }
        b0 = b1; nm0 = nm1; v0 = v1;
        b1 = b2; nm1 = nm2; v1 = v2;
        c0 = n0; c1 = n1;
        hp0 = hp1;
    }
}

// ---------------------------------------------------------------------------
extern "C" void kernel_launch(void* const* d_in, const int* in_sizes, int n_in,
                              void* d_out, int out_size) {
    const float* features = (const float*)d_in[0];
    const float* vals     = (const float*)d_in[1];
    const float* comps1   = (const float*)d_in[2];
    const float* bases1   = (const float*)d_in[3];
    const float* bias1    = (const float*)d_in[4];
    const float* comps2   = (const float*)d_in[5];
    const float* bases2   = (const float*)d_in[6];
    const float* bias2    = (const float*)d_in[7];
    const int*   rows     = (const int*)d_in[8];
    const int*   cols     = (const int*)d_in[9];
    float*       out      = (float*)d_out;
    const int    nnz      = in_sizes[8];

    // 1. weights + zero hist/done/h1
    compute_w_kernel<<<512, 256>>>(comps1, bases1, comps2, bases2);
    // 2. histogram + last-block scan + out=bias2
    hist_kernel<<<256, 256>>>(rows, nnz, out, bias2);
    // 3. bucket scatter (relation-sorted edge list; g_cursor -> bucket ends)
    scatter_kernel<<<(nnz + SCATTER_CHUNK - 1) / SCATTER_CHUNK, 512>>>(
        rows, cols, vals, nnz);
    // 4. layer 1 (register weights, two-level pipeline, pack-free FFMA2)
    layer1_kernel<<<R_REL * CHUNKS, 256>>>(features);
    // 5. bias + relu
    relu_bias_kernel<<<(N_NODES * E_DIM / 4 + 255) / 256, 256>>>(bias1);
    // 6. layer 2
    layer2_kernel<<<R_REL * CHUNKS, 256>>>(out);
}